// round 4
// baseline (speedup 1.0000x reference)
#include <cuda_runtime.h>
#include <cuda_bf16.h>
#include <math.h>

// ---------------------------------------------------------------------------
// Problem constants: B=2, Cin=Cout=64, H=W=80, branches k in {3,5,7}
// ---------------------------------------------------------------------------
#define HH 80
#define WW 80
#define HW 6400
#define CIN 64

typedef unsigned long long u64;

__device__ __forceinline__ void ffma2(u64& d, u64 a, u64 b) {
    asm("fma.rn.f32x2 %0, %1, %2, %0;" : "+l"(d) : "l"(a), "l"(b));
}
__device__ __forceinline__ void addf2(u64& d, u64 a) {
    asm("add.rn.f32x2 %0, %0, %1;" : "+l"(d) : "l"(a));
}
__device__ __forceinline__ float2 unpk(u64 v) {
    float2 r;
    asm("mov.b64 {%0, %1}, %2;" : "=f"(r.x), "=f"(r.y) : "l"(v));
    return r;
}

// ---------------------------------------------------------------------------
// Device scratch
// ---------------------------------------------------------------------------
__device__ float g_om3[2 * 27 * HW];
__device__ float g_om5[2 * 75 * HW];
__device__ float g_om7[2 * 147 * HW];

// conv weights: packed channel pairs
__device__ __align__(16) float2 g_wcv3[64 * 9 * 14];
__device__ __align__(16) float2 g_wcv5[64 * 25 * 38];
__device__ __align__(16) float2 g_wcv7[64 * 49 * 74];

// dcn weights: duplicated pairs, [(t*64+cin)*64 + och] = (w, w)
__device__ __align__(16) float2 g_wd3[9 * 64 * 64];
__device__ __align__(16) float2 g_wd5[25 * 64 * 64];
__device__ __align__(16) float2 g_wd7[49 * 64 * 64];

// precomputed bilinear coefficients/indices: [b][t][pix]
__device__ __align__(16) float4 g_cw3[2 * 9 * HW];
__device__ __align__(16) int4   g_ci3[2 * 9 * HW];
__device__ __align__(16) float4 g_cw5[2 * 25 * HW];
__device__ __align__(16) int4   g_ci5[2 * 25 * HW];
__device__ __align__(16) float4 g_cw7[2 * 49 * HW];
__device__ __align__(16) int4   g_ci7[2 * 49 * HW];

template <int BR> __device__ __forceinline__ float* om_ptr() {
    return BR == 0 ? g_om3 : (BR == 1 ? g_om5 : g_om7);
}
template <int BR> __device__ __forceinline__ float2* wcv_ptr() {
    return BR == 0 ? g_wcv3 : (BR == 1 ? g_wcv5 : g_wcv7);
}
template <int BR> __device__ __forceinline__ float2* wd_ptr() {
    return BR == 0 ? g_wd3 : (BR == 1 ? g_wd5 : g_wd7);
}
template <int BR> __device__ __forceinline__ float4* cw_ptr() {
    return BR == 0 ? g_cw3 : (BR == 1 ? g_cw5 : g_cw7);
}
template <int BR> __device__ __forceinline__ int4* ci_ptr() {
    return BR == 0 ? g_ci3 : (BR == 1 ? g_ci5 : g_ci7);
}

// ---------------------------------------------------------------------------
// Prep: repack weights.
// ---------------------------------------------------------------------------
template <int K, int BR>
__global__ void prep_weights(const float* __restrict__ w_off,
                             const float* __restrict__ w_mask,
                             const float* __restrict__ w_dcn)
{
    constexpr int KK    = K * K;
    constexpr int NCH   = 3 * KK;
    constexpr int NPAIR = (NCH + 1) / 2;
    const int N1 = 64 * K * K * NPAIR;
    const int N2 = KK * 64 * 64;
    float2* wcv = wcv_ptr<BR>();
    float2* wd  = wd_ptr<BR>();

    for (int i = blockIdx.x * blockDim.x + threadIdx.x; i < N1 + N2;
         i += gridDim.x * blockDim.x) {
        if (i < N1) {
            int cp   = i % NPAIR;
            int rest = i / NPAIR;
            int tx   = rest % K;
            int ty   = (rest / K) % K;
            int cin  = rest / (K * K);
            float va = 0.f, vb = 0.f;
            int c1 = 2 * cp, c2 = 2 * cp + 1;
            if (c1 < 2 * KK)      va = w_off[((c1 * 64 + cin) * K + ty) * K + tx];
            else                  va = w_mask[(((c1 - 2 * KK) * 64 + cin) * K + ty) * K + tx];
            if (c2 < NCH) {
                if (c2 < 2 * KK)  vb = w_off[((c2 * 64 + cin) * K + ty) * K + tx];
                else              vb = w_mask[(((c2 - 2 * KK) * 64 + cin) * K + ty) * K + tx];
            }
            wcv[i] = make_float2(va, vb);
        } else {
            int j   = i - N1;
            int och = j & 63;
            int cin = (j >> 6) & 63;
            int t   = j >> 12;
            float v = w_dcn[(och * 64 + cin) * KK + t];
            wd[j] = make_float2(v, v);
        }
    }
}

// ---------------------------------------------------------------------------
// Conv kernel (offset + mask), cin-split across S slices.
// ---------------------------------------------------------------------------
template <int K, int BR, int CGD, int S>
__global__ void __launch_bounds__(CGD * 2 * S)
conv_off_mask(const float* __restrict__ x,
              const float* __restrict__ b_off,
              const float* __restrict__ b_mask)
{
    constexpr int KK    = K * K;
    constexpr int NCH   = 3 * KK;
    constexpr int NPAIR = (NCH + 1) / 2;
    constexpr int TR    = 2;
    constexpr int PAD   = K / 2;
    constexpr int ROWS  = TR + K - 1;
    constexpr int TWH   = 16 + K - 1;
    constexpr int CPS   = 64 / S;

    extern __shared__ __align__(16) float2 xs[];

    const int tid = threadIdx.x;
    const int nth = blockDim.x;
    const int b   = blockIdx.z;
    const int h0  = blockIdx.y * TR;
    const int w0  = blockIdx.x * 16;

    const float* xb = x + (size_t)b * CIN * HW;
    const int hb = h0 - PAD, wb = w0 - PAD;
    for (int i = tid; i < ROWS * 64 * TWH; i += nth) {
        int col  = i % TWH;
        int rest = i / TWH;
        int cin  = rest & 63;
        int row  = rest >> 6;
        int gh = hb + row, gw = wb + col;
        float v = 0.f;
        if (gh >= 0 && gh < HH && gw >= 0 && gw < WW)
            v = xb[(cin * HH + gh) * WW + gw];
        xs[i] = make_float2(v, v);
    }
    __syncthreads();

    const int s  = tid / (CGD * TR);
    const int r  = (tid / CGD) % TR;
    const int cg = tid % CGD;
    const int cp = (cg < NPAIR) ? cg : (NPAIR - 1);

    u64 acc2[16];
#pragma unroll
    for (int p = 0; p < 16; p++) acc2[p] = 0ull;

    const float2* wcv = wcv_ptr<BR>();

    for (int cin = s * CPS; cin < (s + 1) * CPS; cin++) {
#pragma unroll
        for (int ty = 0; ty < K; ty++) {
            const ulonglong2* xrow =
                (const ulonglong2*)&xs[((r + ty) * 64 + cin) * TWH];
            u64 xw[TWH];
#pragma unroll
            for (int q = 0; q < TWH / 2; q++) {
                ulonglong2 t2 = xrow[q];
                xw[2 * q]     = t2.x;
                xw[2 * q + 1] = t2.y;
            }
            const float2* wrow = wcv + (size_t)((cin * K + ty) * K) * NPAIR + cp;
            u64 wt[K];
#pragma unroll
            for (int tx = 0; tx < K; tx++)
                wt[tx] = *(const u64*)(wrow + tx * NPAIR);
#pragma unroll
            for (int tx = 0; tx < K; tx++)
#pragma unroll
                for (int p = 0; p < 16; p++)
                    ffma2(acc2[p], wt[tx], xw[tx + p]);
        }
    }

    // cross-slice reduction through smem
    __syncthreads();
    u64* red = (u64*)xs;
    if (s > 0) {
        const int slot = ((r * CGD + cg) * S + s) * 16;
#pragma unroll
        for (int q = 0; q < 8; q++) {
            ulonglong2 v; v.x = acc2[2 * q]; v.y = acc2[2 * q + 1];
            *(ulonglong2*)&red[slot + 2 * q] = v;
        }
    }
    __syncthreads();

    if (s == 0 && cg < NPAIR) {
#pragma unroll
        for (int s2 = 1; s2 < S; s2++) {
            const int slot = ((r * CGD + cg) * S + s2) * 16;
#pragma unroll
            for (int q = 0; q < 8; q++) {
                ulonglong2 v = *(const ulonglong2*)&red[slot + 2 * q];
                addf2(acc2[2 * q], v.x);
                addf2(acc2[2 * q + 1], v.y);
            }
        }

        const int c1 = 2 * cp;
        const bool two    = (c1 + 1 < NCH);
        const bool ismask = (c1 >= 2 * KK);
        float blo = ismask ? b_mask[c1 - 2 * KK] : b_off[c1];
        float bhi = 0.f;
        if (two) bhi = ismask ? b_mask[c1 + 1 - 2 * KK] : b_off[c1 + 1];

        float lo[16], hi[16];
#pragma unroll
        for (int p = 0; p < 16; p++) {
            float2 v = unpk(acc2[p]);
            lo[p] = v.x + blo;
            hi[p] = v.y + bhi;
        }
        if (ismask) {
#pragma unroll
            for (int p = 0; p < 16; p++) {
                lo[p] = 1.f / (1.f + __expf(-lo[p]));
                hi[p] = 1.f / (1.f + __expf(-hi[p]));
            }
        }
        const int h = h0 + r;
        float* ob = om_ptr<BR>() + (size_t)b * NCH * HW;
        float* p1 = &ob[(c1 * HH + h) * WW + w0];
#pragma unroll
        for (int q = 0; q < 4; q++)
            *(float4*)(p1 + 4 * q) =
                make_float4(lo[4 * q], lo[4 * q + 1], lo[4 * q + 2], lo[4 * q + 3]);
        if (two) {
            float* p2 = p1 + HW;
#pragma unroll
            for (int q = 0; q < 4; q++)
                *(float4*)(p2 + 4 * q) =
                    make_float4(hi[4 * q], hi[4 * q + 1], hi[4 * q + 2], hi[4 * q + 3]);
        }
    }
}

// ---------------------------------------------------------------------------
// Coeff kernel: bilinear weights (mask folded in) + gather indices for all
// (batch, tap, pixel). Fully coalesced; removes all coeff work from deform.
// ---------------------------------------------------------------------------
template <int K, int BR>
__global__ void __launch_bounds__(256)
coeff_kernel()
{
    constexpr int KK  = K * K;
    constexpr int NCH = 3 * KK;
    constexpr int PAD = K / 2;
    const int N = 2 * KK * HW;

    float4* cw = cw_ptr<BR>();
    int4*   ci = ci_ptr<BR>();

    for (int i = blockIdx.x * blockDim.x + threadIdx.x; i < N;
         i += gridDim.x * blockDim.x) {
        int pix = i % HW;
        int t   = (i / HW) % KK;
        int b   = i / (HW * KK);
        int h = pix / WW, w = pix % WW;

        const float* om = om_ptr<BR>() + (size_t)b * NCH * HW;
        float oy = om[(2 * t) * HW + pix];
        float ox = om[(2 * t + 1) * HW + pix];
        float m  = om[(2 * KK + t) * HW + pix];

        float py  = (float)(h - PAD + t / K) + oy;
        float pxf = (float)(w - PAD + t % K) + ox;
        float y0f = floorf(py);
        float x0f = floorf(pxf);
        float ly = py - y0f, lx = pxf - x0f;
        bool vy0 = (y0f >= 0.f) && (y0f <= 79.f);
        bool vy1 = (y0f >= -1.f) && (y0f <= 78.f);
        bool vx0 = (x0f >= 0.f) && (x0f <= 79.f);
        bool vx1 = (x0f >= -1.f) && (x0f <= 78.f);
        int iy0 = (int)fmaxf(fminf(y0f, 80.f), -1.f);
        int ix0 = (int)fmaxf(fminf(x0f, 80.f), -1.f);
        int y0c = max(0, min(79, iy0));
        int y1c = max(0, min(79, iy0 + 1));
        int x0c = max(0, min(79, ix0));
        int x1c = max(0, min(79, ix0 + 1));
        float wy0 = (1.f - ly) * m, wy1 = ly * m;
        float wx0 = 1.f - lx, wx1 = lx;
        float4 a;
        a.x = (vy0 && vx0) ? wy0 * wx0 : 0.f;
        a.y = (vy0 && vx1) ? wy0 * wx1 : 0.f;
        a.z = (vy1 && vx0) ? wy1 * wx0 : 0.f;
        a.w = (vy1 && vx1) ? wy1 * wx1 : 0.f;
        int4 o4;
        o4.x = y0c * WW + x0c;
        o4.y = y0c * WW + x1c;
        o4.z = y1c * WW + x0c;
        o4.w = y1c * WW + x1c;
        cw[i] = a;
        ci[i] = o4;
    }
}

// ---------------------------------------------------------------------------
// Deform kernel. CTA = 128 threads, 2x16 pixel tile. Double-buffered s,
// ONE sync per tap. Coeffs are 2 fixed LDG.128 per thread per tap (each
// thread's pixel is invariant: px = tid & 31).
// ---------------------------------------------------------------------------
template <int K, int BR>
__global__ void __launch_bounds__(128)
deform_gemm(const float* __restrict__ x, float* __restrict__ out)
{
    constexpr int KK    = K * K;
    constexpr int CBASE = BR * 64;

    __shared__ __align__(16) float s[2][64][32];

    const int tid = threadIdx.x;
    const int b   = blockIdx.z;
    const int h0  = blockIdx.y * 2;
    const int w0  = blockIdx.x * 16;

    const int px   = tid & 31;          // gather pixel (fixed per thread)
    const int cinb = tid >> 5;          // gather cin base (cin = cinb + 4j)
    const int og   = tid >> 3;          // 16 groups of 4 output channels
    const int pg   = tid & 7;           // 8 groups of 4 pixels

    const float2* wd = wd_ptr<BR>();
    const float*  xb = x + (size_t)b * CIN * HW;

    // coeff base index for this thread's pixel
    const int prow = px >> 4, pcol = px & 15;
    const size_t cbase = ((size_t)b * KK) * HW + (h0 + prow) * WW + (w0 + pcol);
    const float4* cw = cw_ptr<BR>();
    const int4*   ci = ci_ptr<BR>();

    u64 acc2[4][2] = {};

    // prologue: gather tap 0
    {
        float4 a = cw[cbase];
        int4  o4 = ci[cbase];
#pragma unroll 4
        for (int j = 0; j < 16; j++) {
            int cin = cinb + j * 4;
            const float* xc = xb + cin * HW;
            s[0][cin][px] = a.x * xc[o4.x] + a.y * xc[o4.y] +
                            a.z * xc[o4.z] + a.w * xc[o4.w];
        }
    }
    __syncthreads();

    for (int t = 0; t < KK; t++) {
        // gather next tap into the other buffer (overlaps this tap's GEMM issue)
        if (t + 1 < KK) {
            float4 a = cw[cbase + (size_t)(t + 1) * HW];
            int4  o4 = ci[cbase + (size_t)(t + 1) * HW];
            float* sd = &s[(t + 1) & 1][0][px];
#pragma unroll 4
            for (int j = 0; j < 16; j++) {
                int cin = cinb + j * 4;
                const float* xc = xb + cin * HW;
                sd[cin * 32] = a.x * xc[o4.x] + a.y * xc[o4.y] +
                               a.z * xc[o4.z] + a.w * xc[o4.w];
            }
        }

        // GEMM: acc[4 och][4 px] += dup(w) * s-pairs
        const float2* wt = wd + (size_t)t * 4096;
        const float (*sb)[32] = s[t & 1];
#pragma unroll 8
        for (int cin = 0; cin < 64; cin++) {
            ulonglong2 sv = *(const ulonglong2*)&sb[cin][pg * 4];
            const ulonglong2* wr = (const ulonglong2*)(wt + cin * 64 + og * 4);
            ulonglong2 w01 = wr[0];
            ulonglong2 w23 = wr[1];
            ffma2(acc2[0][0], w01.x, sv.x); ffma2(acc2[0][1], w01.x, sv.y);
            ffma2(acc2[1][0], w01.y, sv.x); ffma2(acc2[1][1], w01.y, sv.y);
            ffma2(acc2[2][0], w23.x, sv.x); ffma2(acc2[2][1], w23.x, sv.y);
            ffma2(acc2[3][0], w23.y, sv.x); ffma2(acc2[3][1], w23.y, sv.y);
        }
        __syncthreads();
    }

    // write output: 4 och x 4 px per thread
    const int row  = pg >> 2;
    const int colb = (pg & 3) * 4;
    float* ob = out + ((size_t)(b * 192 + CBASE + og * 4)) * HW +
                (h0 + row) * WW + w0 + colb;
#pragma unroll
    for (int o = 0; o < 4; o++) {
        float2 v0 = unpk(acc2[o][0]);
        float2 v1 = unpk(acc2[o][1]);
        *(float4*)(ob + (size_t)o * HW) = make_float4(v0.x, v0.y, v1.x, v1.y);
    }
}

// ---------------------------------------------------------------------------
// Launch (single stream; no stream/event creation — allocation guard).
// ---------------------------------------------------------------------------
extern "C" void kernel_launch(void* const* d_in, const int* in_sizes, int n_in,
                              void* d_out, int out_size)
{
    (void)in_sizes; (void)n_in; (void)out_size;

    const float* x       = (const float*)d_in[0];
    const float* w_off3  = (const float*)d_in[1];
    const float* b_off3  = (const float*)d_in[2];
    const float* w_mask3 = (const float*)d_in[3];
    const float* b_mask3 = (const float*)d_in[4];
    const float* w_dcn3  = (const float*)d_in[5];
    const float* w_off5  = (const float*)d_in[6];
    const float* b_off5  = (const float*)d_in[7];
    const float* w_mask5 = (const float*)d_in[8];
    const float* b_mask5 = (const float*)d_in[9];
    const float* w_dcn5  = (const float*)d_in[10];
    const float* w_off7  = (const float*)d_in[11];
    const float* b_off7  = (const float*)d_in[12];
    const float* w_mask7 = (const float*)d_in[13];
    const float* b_mask7 = (const float*)d_in[14];
    const float* w_dcn7  = (const float*)d_in[15];
    float* out = (float*)d_out;

    const int smem3 = 4 * 64 * 18 * 8;   // 36.9 KB
    const int smem5 = 6 * 64 * 20 * 8;   // 61.4 KB
    const int smem7 = 8 * 64 * 22 * 8;   // 90.1 KB
    cudaFuncSetAttribute((const void*)conv_off_mask<3, 0, 16, 4>,
                         cudaFuncAttributeMaxDynamicSharedMemorySize, smem3);
    cudaFuncSetAttribute((const void*)conv_off_mask<5, 1, 40, 4>,
                         cudaFuncAttributeMaxDynamicSharedMemorySize, smem5);
    cudaFuncSetAttribute((const void*)conv_off_mask<7, 2, 80, 2>,
                         cudaFuncAttributeMaxDynamicSharedMemorySize, smem7);

    // weight repacking
    const int n3 = 64 * 9 * 14 + 9 * 4096;
    const int n5 = 64 * 25 * 38 + 25 * 4096;
    const int n7 = 64 * 49 * 74 + 49 * 4096;
    prep_weights<3, 0><<<(n3 + 255) / 256, 256>>>(w_off3, w_mask3, w_dcn3);
    prep_weights<5, 1><<<(n5 + 255) / 256, 256>>>(w_off5, w_mask5, w_dcn5);
    prep_weights<7, 2><<<(n7 + 255) / 256, 256>>>(w_off7, w_mask7, w_dcn7);

    // offset+mask convs, then coeff kernels (need conv outputs)
    conv_off_mask<3, 0, 16, 4><<<dim3(5, 40, 2), 128, smem3>>>(x, b_off3, b_mask3);
    conv_off_mask<5, 1, 40, 4><<<dim3(5, 40, 2), 320, smem5>>>(x, b_off5, b_mask5);
    conv_off_mask<7, 2, 80, 2><<<dim3(5, 40, 2), 320, smem7>>>(x, b_off7, b_mask7);

    coeff_kernel<3, 0><<<(2 * 9 * HW + 255) / 256, 256>>>();
    coeff_kernel<5, 1><<<(2 * 25 * HW + 255) / 256, 256>>>();
    coeff_kernel<7, 2><<<(2 * 49 * HW + 255) / 256, 256>>>();

    // deformable sampling + DCN einsum
    deform_gemm<3, 0><<<dim3(5, 40, 2), 128>>>(x, out);
    deform_gemm<5, 1><<<dim3(5, 40, 2), 128>>>(x, out);
    deform_gemm<7, 2><<<dim3(5, 40, 2), 128>>>(x, out);
}